// round 1
// baseline (speedup 1.0000x reference)
#include <cuda_runtime.h>
#include <cstdint>

// CostVolume: out[b,d,h,x] = (1/128) * sum_c L[b,c,h,x]*R[b,c,h,x-d], x>=d else 0
// B=8 C=128 H=128 W=240 V=48
#define B_  8
#define C_  128
#define H_  128
#define W_  240
#define V_  48
#define HW_ (H_*W_)

#define CC   16            // channels per chunk
#define NCH  (C_/CC)       // 8 chunks
#define THREADS 128
#define IT   24            // disparities per thread (2 i-groups)
#define RW   288           // sR row width: 48 zero pad + 240 data

__device__ __forceinline__ unsigned long long pk(float lo, float hi) {
    unsigned long long r;
    asm("mov.b64 %0, {%1, %2};" : "=l"(r) : "f"(lo), "f"(hi));
    return r;
}
__device__ __forceinline__ void upk(unsigned long long v, float& lo, float& hi) {
    asm("mov.b64 {%0, %1}, %2;" : "=f"(lo), "=f"(hi) : "l"(v));
}
__device__ __forceinline__ void fma2(unsigned long long& acc,
                                     unsigned long long a, unsigned long long b) {
    asm("fma.rn.f32x2 %0, %1, %2, %0;" : "+l"(acc) : "l"(a), "l"(b));
}
__device__ __forceinline__ void cpasync16(uint32_t saddr, const void* g) {
    asm volatile("cp.async.cg.shared.global [%0], [%1], 16;" :: "r"(saddr), "l"(g));
}

__global__ void __launch_bounds__(THREADS)
cv_kernel(const float* __restrict__ L, const float* __restrict__ R,
          float* __restrict__ out)
{
    extern __shared__ float smem[];
    float* sL = smem;                 // [2][CC][W_]   = 2*16*240 floats
    float* sR = smem + 2 * CC * W_;   // [2][CC][RW]   = 2*16*288 floats

    const int tid = threadIdx.x;
    const int h = blockIdx.x;
    const int b = blockIdx.y;

    const int xg = tid & 63;          // 0..63 (60 active)
    const int ig = tid >> 6;          // 0..1
    const int i0 = ig * IT;
    const int xb = xg * 4;
    const bool act = (xg < 60);

    const float* Lbase = L + ((size_t)b * C_ * H_ + h) * W_;  // + c*HW_ + x
    const float* Rbase = R + ((size_t)b * C_ * H_ + h) * W_;

    // Zero the left pad of sR (j<0 -> 0), both buffers, once.
    for (int idx = tid; idx < 2 * CC * 48; idx += THREADS) {
        int buf = idx / (CC * 48);
        int rem = idx - buf * (CC * 48);
        int r = rem / 48, k = rem - r * 48;
        sR[buf * (CC * RW) + r * RW + k] = 0.0f;
    }

    unsigned long long acc[IT][2];
    #pragma unroll
    for (int ii = 0; ii < IT; ii++) { acc[ii][0] = 0ull; acc[ii][1] = 0ull; }

    auto issue_load = [&](int ch, int buf) {
        const int c0 = ch * CC;
        #pragma unroll
        for (int q = 0; q < 15; q++) {           // 1920 float4 ops / 128 thr
            int f = tid + q * THREADS;
            if (f < 960) {                        // L tile
                int r = f / 60, col = (f - r * 60) * 4;
                uint32_t d = (uint32_t)__cvta_generic_to_shared(
                    &sL[buf * (CC * W_) + r * W_ + col]);
                cpasync16(d, Lbase + (size_t)(c0 + r) * HW_ + col);
            } else {                              // R tile (offset 48)
                int f2 = f - 960;
                int r = f2 / 60, col = (f2 - r * 60) * 4;
                uint32_t d = (uint32_t)__cvta_generic_to_shared(
                    &sR[buf * (CC * RW) + r * RW + 48 + col]);
                cpasync16(d, Rbase + (size_t)(c0 + r) * HW_ + col);
            }
        }
        asm volatile("cp.async.commit_group;");
    };

    issue_load(0, 0);

    #pragma unroll 1
    for (int ch = 0; ch < NCH; ch++) {
        const int buf = ch & 1;
        if (ch + 1 < NCH) {
            issue_load(ch + 1, (ch + 1) & 1);
            asm volatile("cp.async.wait_group 1;");
        } else {
            asm volatile("cp.async.wait_group 0;");
        }
        __syncthreads();

        if (act) {
            const float* bL = &sL[buf * (CC * W_)];
            const float* bR = &sR[buf * (CC * RW)];
            const int ab = xb - i0 + 24;  // aligned (mod 4) window base in sR row
            #pragma unroll
            for (int cc = 0; cc < CC; cc++) {
                float4 Lq = *(const float4*)(bL + cc * W_ + xb);
                unsigned long long La = pk(Lq.x, Lq.y);
                unsigned long long Lb = pk(Lq.z, Lq.w);

                float r_[28];
                #pragma unroll
                for (int m = 0; m < 7; m++) {
                    float4 qv = *(const float4*)(bR + cc * RW + ab + 4 * m);
                    r_[4*m+0] = qv.x; r_[4*m+1] = qv.y;
                    r_[4*m+2] = qv.z; r_[4*m+3] = qv.w;
                }
                // r_[k] = R[xb - i0 + k - 24]
                unsigned long long pr[27];
                #pragma unroll
                for (int k = 1; k <= 26; k++) pr[k] = pk(r_[k], r_[k + 1]);

                #pragma unroll
                for (int ii = 0; ii < IT; ii++) {
                    // d = i0+ii; x pair (xb,xb+1): R pair at k=24-ii
                    fma2(acc[ii][0], La, pr[24 - ii]);
                    // x pair (xb+2,xb+3): R pair at k=26-ii
                    fma2(acc[ii][1], Lb, pr[26 - ii]);
                }
            }
        }
        __syncthreads();
    }

    if (act) {
        const float s = 1.0f / 128.0f;
        #pragma unroll
        for (int ii = 0; ii < IT; ii++) {
            int d = i0 + ii;
            float a0, a1, a2, a3;
            upk(acc[ii][0], a0, a1);
            upk(acc[ii][1], a2, a3);
            float4 o;
            o.x = a0 * s; o.y = a1 * s; o.z = a2 * s; o.w = a3 * s;
            *(float4*)(out + (((size_t)b * V_ + d) * H_ + h) * W_ + xb) = o;
        }
    }
}

extern "C" void kernel_launch(void* const* d_in, const int* in_sizes, int n_in,
                              void* d_out, int out_size)
{
    const float* L = (const float*)d_in[0];
    const float* R = (const float*)d_in[1];
    float* out = (float*)d_out;

    const int smem_bytes = (2 * CC * W_ + 2 * CC * RW) * (int)sizeof(float); // 67584
    cudaFuncSetAttribute(cv_kernel, cudaFuncAttributeMaxDynamicSharedMemorySize,
                         smem_bytes);
    cv_kernel<<<dim3(H_, B_), THREADS, smem_bytes>>>(L, R, out);
}